// round 1
// baseline (speedup 1.0000x reference)
#include <cuda_runtime.h>

#define NNODES 40000
#define NEDGES 640000
#define HID    128
#define MROWS  80000   // BATCH * NNODES

// ---------------- device scratch (no allocations allowed) ----------------
__device__ float g_X[(size_t)MROWS * HID];     // activations x
__device__ float g_NET[(size_t)MROWS * HID];   // block intermediate net
__device__ float g_AGG[(size_t)MROWS * HID];   // spmm output
__device__ int   g_rowptr[NNODES + 1];
__device__ int   g_cursor[NNODES];
__device__ int   g_cols[NEDGES];
__device__ float g_vals[NEDGES];

// ---------------- CSR build ----------------
__global__ void k_zero_cursor() {
    int i = blockIdx.x * blockDim.x + threadIdx.x;
    if (i < NNODES) g_cursor[i] = 0;
}

__global__ void k_hist(const int* __restrict__ rows) {
    int i = blockIdx.x * blockDim.x + threadIdx.x;
    if (i < NEDGES) atomicAdd(&g_cursor[rows[i]], 1);
}

// single-block scan over 40000 counts -> exclusive rowptr, cursor = rowptr base
__global__ void k_scan() {
    __shared__ int wsum[32];
    __shared__ int s_carry;
    int tid = threadIdx.x;
    int lane = tid & 31, wid = tid >> 5;
    if (tid == 0) { s_carry = 0; g_rowptr[0] = 0; }
    __syncthreads();
    for (int start = 0; start < NNODES; start += 1024) {
        int i = start + tid;
        int c = (i < NNODES) ? g_cursor[i] : 0;
        int v = c;
        #pragma unroll
        for (int o = 1; o < 32; o <<= 1) {
            int t = __shfl_up_sync(0xffffffffu, v, o);
            if (lane >= o) v += t;
        }
        if (lane == 31) wsum[wid] = v;
        __syncthreads();
        if (wid == 0) {
            int w = wsum[lane];
            #pragma unroll
            for (int o = 1; o < 32; o <<= 1) {
                int t = __shfl_up_sync(0xffffffffu, w, o);
                if (lane >= o) w += t;
            }
            wsum[lane] = w;
        }
        __syncthreads();
        int incl = v + (wid > 0 ? wsum[wid - 1] : 0) + s_carry;
        if (i < NNODES) { g_rowptr[i + 1] = incl; g_cursor[i] = incl - c; }
        int chunk_total = wsum[31];
        __syncthreads();   // everyone done reading wsum/s_carry
        if (tid == 0) s_carry += chunk_total;
        __syncthreads();
    }
}

__global__ void k_scatter(const int* __restrict__ rows, const int* __restrict__ cols,
                          const float* __restrict__ vals) {
    int i = blockIdx.x * blockDim.x + threadIdx.x;
    if (i < NEDGES) {
        int r = rows[i];
        int pos = atomicAdd(&g_cursor[r], 1);
        g_cols[pos] = cols[i];
        g_vals[pos] = vals[i];
    }
}

// ---------------- init linear 3 -> 128 ----------------
__global__ void k_init(const float* __restrict__ p, const float* __restrict__ Wi,
                       const float* __restrict__ bi) {
    int idx = blockIdx.x * blockDim.x + threadIdx.x;
    if (idx >= MROWS * 32) return;
    int m = idx >> 5;
    int h = (idx & 31) * 4;
    float p0 = p[m * 3 + 0], p1 = p[m * 3 + 1], p2 = p[m * 3 + 2];
    float4 w0 = *(const float4*)&Wi[0 * HID + h];
    float4 w1 = *(const float4*)&Wi[1 * HID + h];
    float4 w2 = *(const float4*)&Wi[2 * HID + h];
    float4 bb = *(const float4*)&bi[h];
    float4 o;
    o.x = fmaf(p0, w0.x, fmaf(p1, w1.x, fmaf(p2, w2.x, bb.x)));
    o.y = fmaf(p0, w0.y, fmaf(p1, w1.y, fmaf(p2, w2.y, bb.y)));
    o.z = fmaf(p0, w0.z, fmaf(p1, w1.z, fmaf(p2, w2.z, bb.z)));
    o.w = fmaf(p0, w0.w, fmaf(p1, w1.w, fmaf(p2, w2.w, bb.w)));
    *(float4*)&g_X[(size_t)m * HID + h] = o;
}

// ---------------- spmm: AGG = A * relu(src), both batches per warp ----------------
__global__ void k_spmm(int sel) {
    const float* __restrict__ src = sel ? g_NET : g_X;
    int w = (blockIdx.x * blockDim.x + threadIdx.x) >> 5;
    int lane = threadIdx.x & 31;
    if (w >= NNODES) return;
    int s = g_rowptr[w], e = g_rowptr[w + 1];
    int off = lane * 4;
    float4 a0 = make_float4(0.f, 0.f, 0.f, 0.f);
    float4 a1 = make_float4(0.f, 0.f, 0.f, 0.f);
    for (int j = s; j < e; ++j) {
        int c = g_cols[j];
        float v = g_vals[j];
        float4 x0 = *(const float4*)&src[(size_t)c * HID + off];
        float4 x1 = *(const float4*)&src[((size_t)NNODES + c) * HID + off];
        a0.x = fmaf(v, fmaxf(x0.x, 0.f), a0.x);
        a0.y = fmaf(v, fmaxf(x0.y, 0.f), a0.y);
        a0.z = fmaf(v, fmaxf(x0.z, 0.f), a0.z);
        a0.w = fmaf(v, fmaxf(x0.w, 0.f), a0.w);
        a1.x = fmaf(v, fmaxf(x1.x, 0.f), a1.x);
        a1.y = fmaf(v, fmaxf(x1.y, 0.f), a1.y);
        a1.z = fmaf(v, fmaxf(x1.z, 0.f), a1.z);
        a1.w = fmaf(v, fmaxf(x1.w, 0.f), a1.w);
    }
    *(float4*)&g_AGG[(size_t)w * HID + off] = a0;
    *(float4*)&g_AGG[((size_t)NNODES + w) * HID + off] = a1;
}

// ---------------- fused GEMM: C = relu(A1)@Ws + AGG@Wf + bias (+ residual) ----------------
// mode 0: A1 = X,   C = NET, no residual
// mode 1: A1 = NET, C = X,   residual (C holds old X, read before write)
struct Frag { float4 va0, va1, vb0, vb1; };

__device__ __forceinline__ void fetch_tile(int t, const float* __restrict__ A1,
                                           const float* __restrict__ Ws,
                                           const float* __restrict__ Wf,
                                           int m0, int am, int ak4, int bk, int bn4,
                                           Frag& f) {
    int kg = t * 16;
    int ka = kg + ak4;
    if (ka < HID) {
        f.va0 = *(const float4*)&A1[(size_t)(m0 + am) * HID + ka];
        f.va1 = *(const float4*)&A1[(size_t)(m0 + am + 64) * HID + ka];
        f.va0.x = fmaxf(f.va0.x, 0.f); f.va0.y = fmaxf(f.va0.y, 0.f);
        f.va0.z = fmaxf(f.va0.z, 0.f); f.va0.w = fmaxf(f.va0.w, 0.f);
        f.va1.x = fmaxf(f.va1.x, 0.f); f.va1.y = fmaxf(f.va1.y, 0.f);
        f.va1.z = fmaxf(f.va1.z, 0.f); f.va1.w = fmaxf(f.va1.w, 0.f);
    } else {
        f.va0 = *(const float4*)&g_AGG[(size_t)(m0 + am) * HID + (ka - HID)];
        f.va1 = *(const float4*)&g_AGG[(size_t)(m0 + am + 64) * HID + (ka - HID)];
    }
    const float* W = (kg < HID) ? Ws : Wf;
    int kb = kg & (HID - 1);
    f.vb0 = *(const float4*)&W[(size_t)(kb + bk) * 128 + bn4];
    f.vb1 = *(const float4*)&W[(size_t)(kb + bk + 8) * 128 + bn4];
}

__global__ void __launch_bounds__(256) k_gemm(int mode,
        const float* __restrict__ Ws, const float* __restrict__ Wf,
        const float* __restrict__ bs, const float* __restrict__ bf) {
    const float* __restrict__ A1 = mode ? g_NET : g_X;
    float* __restrict__ C = mode ? g_X : g_NET;

    __shared__ float As[2][16][132];
    __shared__ float Bs[2][16][128];

    const int tid = threadIdx.x;
    const int m0 = blockIdx.x * 128;
    const int ak4 = (tid & 3) * 4;     // k offset in tile
    const int am  = tid >> 2;          // 0..63
    const int bn4 = (tid & 31) * 4;    // n offset
    const int bk  = tid >> 5;          // 0..7
    const int tr  = (tid >> 4) * 4;    // row frag base
    const int tc  = (tid & 15) * 4;    // col frag base

    float acc[8][8];
    #pragma unroll
    for (int i = 0; i < 8; ++i)
        #pragma unroll
        for (int j = 0; j < 8; ++j) acc[i][j] = 0.f;

    Frag f;
    fetch_tile(0, A1, Ws, Wf, m0, am, ak4, bk, bn4, f);
    {
        As[0][ak4 + 0][am] = f.va0.x; As[0][ak4 + 1][am] = f.va0.y;
        As[0][ak4 + 2][am] = f.va0.z; As[0][ak4 + 3][am] = f.va0.w;
        As[0][ak4 + 0][am + 64] = f.va1.x; As[0][ak4 + 1][am + 64] = f.va1.y;
        As[0][ak4 + 2][am + 64] = f.va1.z; As[0][ak4 + 3][am + 64] = f.va1.w;
        *(float4*)&Bs[0][bk][bn4] = f.vb0;
        *(float4*)&Bs[0][bk + 8][bn4] = f.vb1;
    }
    __syncthreads();

    int buf = 0;
    #pragma unroll 1
    for (int t = 0; t < 16; ++t) {
        Frag nf;
        if (t < 15) fetch_tile(t + 1, A1, Ws, Wf, m0, am, ak4, bk, bn4, nf);
        #pragma unroll
        for (int k = 0; k < 16; ++k) {
            float a[8], b[8];
            *(float4*)&a[0] = *(const float4*)&As[buf][k][tr];
            *(float4*)&a[4] = *(const float4*)&As[buf][k][tr + 64];
            *(float4*)&b[0] = *(const float4*)&Bs[buf][k][tc];
            *(float4*)&b[4] = *(const float4*)&Bs[buf][k][tc + 64];
            #pragma unroll
            for (int i = 0; i < 8; ++i)
                #pragma unroll
                for (int j = 0; j < 8; ++j)
                    acc[i][j] = fmaf(a[i], b[j], acc[i][j]);
        }
        if (t < 15) {
            int nb = buf ^ 1;
            As[nb][ak4 + 0][am] = nf.va0.x; As[nb][ak4 + 1][am] = nf.va0.y;
            As[nb][ak4 + 2][am] = nf.va0.z; As[nb][ak4 + 3][am] = nf.va0.w;
            As[nb][ak4 + 0][am + 64] = nf.va1.x; As[nb][ak4 + 1][am + 64] = nf.va1.y;
            As[nb][ak4 + 2][am + 64] = nf.va1.z; As[nb][ak4 + 3][am + 64] = nf.va1.w;
            *(float4*)&Bs[nb][bk][bn4] = nf.vb0;
            *(float4*)&Bs[nb][bk + 8][bn4] = nf.vb1;
        }
        __syncthreads();
        buf ^= 1;
    }

    float bias[8];
    #pragma unroll
    for (int j = 0; j < 4; ++j) {
        bias[j]     = bs[tc + j] + bf[tc + j];
        bias[4 + j] = bs[64 + tc + j] + bf[64 + tc + j];
    }
    #pragma unroll
    for (int ih = 0; ih < 2; ++ih)
        #pragma unroll
        for (int iv = 0; iv < 4; ++iv) {
            int m = m0 + ih * 64 + tr + iv;
            int ai = ih * 4 + iv;
            #pragma unroll
            for (int jh = 0; jh < 2; ++jh) {
                int n = jh * 64 + tc;
                float4 o;
                o.x = acc[ai][jh * 4 + 0] + bias[jh * 4 + 0];
                o.y = acc[ai][jh * 4 + 1] + bias[jh * 4 + 1];
                o.z = acc[ai][jh * 4 + 2] + bias[jh * 4 + 2];
                o.w = acc[ai][jh * 4 + 3] + bias[jh * 4 + 3];
                if (mode) {
                    float4 r = *(const float4*)&C[(size_t)m * HID + n];
                    o.x += r.x; o.y += r.y; o.z += r.z; o.w += r.w;
                }
                *(float4*)&C[(size_t)m * HID + n] = o;
            }
        }
}

// ---------------- final layer 128 -> 3, warp per row ----------------
__global__ void k_final(const float* __restrict__ Wfo, const float* __restrict__ bfo,
                        const float* __restrict__ Wso, const float* __restrict__ bso,
                        float* __restrict__ out) {
    int w = (blockIdx.x * blockDim.x + threadIdx.x) >> 5;
    int lane = threadIdx.x & 31;
    if (w >= MROWS) return;
    int k0 = lane * 4;
    float4 x = *(const float4*)&g_X[(size_t)w * HID + k0];
    float4 a = *(const float4*)&g_AGG[(size_t)w * HID + k0];
    float xv[4] = { fmaxf(x.x, 0.f), fmaxf(x.y, 0.f), fmaxf(x.z, 0.f), fmaxf(x.w, 0.f) };
    float av[4] = { a.x, a.y, a.z, a.w };
    float s0 = 0.f, s1 = 0.f, s2 = 0.f;
    #pragma unroll
    for (int i = 0; i < 4; ++i) {
        int k = k0 + i;
        s0 += xv[i] * Wso[k * 3 + 0] + av[i] * Wfo[k * 3 + 0];
        s1 += xv[i] * Wso[k * 3 + 1] + av[i] * Wfo[k * 3 + 1];
        s2 += xv[i] * Wso[k * 3 + 2] + av[i] * Wfo[k * 3 + 2];
    }
    #pragma unroll
    for (int o = 16; o; o >>= 1) {
        s0 += __shfl_down_sync(0xffffffffu, s0, o);
        s1 += __shfl_down_sync(0xffffffffu, s1, o);
        s2 += __shfl_down_sync(0xffffffffu, s2, o);
    }
    if (lane == 0) {
        out[(size_t)w * 3 + 0] = s0 + bso[0] + bfo[0];
        out[(size_t)w * 3 + 1] = s1 + bso[1] + bfo[1];
        out[(size_t)w * 3 + 2] = s2 + bso[2] + bfo[2];
    }
}

// ---------------- launch ----------------
extern "C" void kernel_launch(void* const* d_in, const int* in_sizes, int n_in,
                              void* d_out, int out_size) {
    const float* p        = (const float*)d_in[0];
    const float* adj_vals = (const float*)d_in[1];
    const int*   e_rows   = (const int*)d_in[2];
    const int*   e_cols   = (const int*)d_in[3];
    const float* W_init   = (const float*)d_in[4];
    const float* b_init   = (const float*)d_in[5];
    const float* Wf_b     = (const float*)d_in[6];
    const float* bf_b     = (const float*)d_in[7];
    const float* Ws_b     = (const float*)d_in[8];
    const float* bs_b     = (const float*)d_in[9];
    const float* Wf_out   = (const float*)d_in[10];
    const float* bf_out   = (const float*)d_in[11];
    const float* Ws_out   = (const float*)d_in[12];
    const float* bs_out   = (const float*)d_in[13];
    float* out = (float*)d_out;

    // CSR build (every call: no caching allowed)
    k_zero_cursor<<<(NNODES + 255) / 256, 256>>>();
    k_hist<<<(NEDGES + 255) / 256, 256>>>(e_rows);
    k_scan<<<1, 1024>>>();
    k_scatter<<<(NEDGES + 255) / 256, 256>>>(e_rows, e_cols, adj_vals);

    // x = p @ W_init + b_init
    k_init<<<(MROWS * 32 + 255) / 256, 256>>>(p, W_init, b_init);

    // 4 graph-conv layers (two residual blocks)
    for (int L = 0; L < 4; ++L) {
        int mode = L & 1;   // 0: X->NET, 1: NET->X (+residual)
        k_spmm<<<NNODES / 8, 256>>>(mode);
        k_gemm<<<MROWS / 128, 256>>>(mode,
                                     Ws_b + (size_t)L * HID * HID,
                                     Wf_b + (size_t)L * HID * HID,
                                     bs_b + (size_t)L * HID,
                                     bf_b + (size_t)L * HID);
    }

    // final 128 -> 3
    k_spmm<<<NNODES / 8, 256>>>(0);
    k_final<<<(MROWS * 32 + 255) / 256, 256>>>(Wf_out, bf_out, Ws_out, bs_out, out);
}

// round 3
// speedup vs baseline: 1.0335x; 1.0335x over previous
#include <cuda_runtime.h>
#include <cstdint>

#define NNODES 40000
#define NEDGES 640000
#define HID    128
#define MROWS  80000   // BATCH * NNODES

// ---------------- device scratch (no allocations allowed) ----------------
__device__ float g_X[(size_t)MROWS * HID];     // activations x
__device__ float g_NET[(size_t)MROWS * HID];   // block intermediate net
__device__ float g_AGG[(size_t)MROWS * HID];   // spmm output / final Yf scratch
__device__ int   g_rowptr[NNODES + 1];
__device__ int   g_cursor[NNODES];
__device__ int   g_cols[NEDGES];
__device__ float g_vals[NEDGES];

// ---------------- packed fp32x2 helpers ----------------
#define FMA2(acc, a2, b2) \
    asm("fma.rn.f32x2 %0, %1, %2, %0;" : "+l"(acc) : "l"(a2), "l"(b2))
#define PACK2(d, f) \
    asm("mov.b64 %0, {%1, %1};" : "=l"(d) : "f"(f))
#define UNPACK2(lo, hi, v) \
    asm("mov.b64 {%0, %1}, %2;" : "=f"(lo), "=f"(hi) : "l"(v))

// ---------------- CSR build ----------------
__global__ void k_zero_cursor() {
    int i = blockIdx.x * blockDim.x + threadIdx.x;
    if (i < NNODES) g_cursor[i] = 0;
}

__global__ void k_hist(const int* __restrict__ rows) {
    int i = blockIdx.x * blockDim.x + threadIdx.x;
    if (i < NEDGES) atomicAdd(&g_cursor[rows[i]], 1);
}

__global__ void k_scan() {
    __shared__ int wsum[32];
    __shared__ int s_carry;
    int tid = threadIdx.x;
    int lane = tid & 31, wid = tid >> 5;
    if (tid == 0) { s_carry = 0; g_rowptr[0] = 0; }
    __syncthreads();
    for (int start = 0; start < NNODES; start += 1024) {
        int i = start + tid;
        int c = (i < NNODES) ? g_cursor[i] : 0;
        int v = c;
        #pragma unroll
        for (int o = 1; o < 32; o <<= 1) {
            int t = __shfl_up_sync(0xffffffffu, v, o);
            if (lane >= o) v += t;
        }
        if (lane == 31) wsum[wid] = v;
        __syncthreads();
        if (wid == 0) {
            int w = wsum[lane];
            #pragma unroll
            for (int o = 1; o < 32; o <<= 1) {
                int t = __shfl_up_sync(0xffffffffu, w, o);
                if (lane >= o) w += t;
            }
            wsum[lane] = w;
        }
        __syncthreads();
        int incl = v + (wid > 0 ? wsum[wid - 1] : 0) + s_carry;
        if (i < NNODES) { g_rowptr[i + 1] = incl; g_cursor[i] = incl - c; }
        int chunk_total = wsum[31];
        __syncthreads();
        if (tid == 0) s_carry += chunk_total;
        __syncthreads();
    }
}

__global__ void k_scatter(const int* __restrict__ rows, const int* __restrict__ cols,
                          const float* __restrict__ vals) {
    int i = blockIdx.x * blockDim.x + threadIdx.x;
    if (i < NEDGES) {
        int r = rows[i];
        int pos = atomicAdd(&g_cursor[r], 1);
        g_cols[pos] = cols[i];
        g_vals[pos] = vals[i];
    }
}

// ---------------- init linear 3 -> 128 ----------------
__global__ void k_init(const float* __restrict__ p, const float* __restrict__ Wi,
                       const float* __restrict__ bi) {
    int idx = blockIdx.x * blockDim.x + threadIdx.x;
    if (idx >= MROWS * 32) return;
    int m = idx >> 5;
    int h = (idx & 31) * 4;
    float p0 = p[m * 3 + 0], p1 = p[m * 3 + 1], p2 = p[m * 3 + 2];
    float4 w0 = *(const float4*)&Wi[0 * HID + h];
    float4 w1 = *(const float4*)&Wi[1 * HID + h];
    float4 w2 = *(const float4*)&Wi[2 * HID + h];
    float4 bb = *(const float4*)&bi[h];
    float4 o;
    o.x = fmaf(p0, w0.x, fmaf(p1, w1.x, fmaf(p2, w2.x, bb.x)));
    o.y = fmaf(p0, w0.y, fmaf(p1, w1.y, fmaf(p2, w2.y, bb.y)));
    o.z = fmaf(p0, w0.z, fmaf(p1, w1.z, fmaf(p2, w2.z, bb.z)));
    o.w = fmaf(p0, w0.w, fmaf(p1, w1.w, fmaf(p2, w2.w, bb.w)));
    *(float4*)&g_X[(size_t)m * HID + h] = o;
}

// ---------------- spmm: AGG = A * relu(src), both batches per warp ----------------
__global__ void k_spmm(int sel) {
    const float* __restrict__ src = sel ? g_NET : g_X;
    int w = (blockIdx.x * blockDim.x + threadIdx.x) >> 5;
    int lane = threadIdx.x & 31;
    if (w >= NNODES) return;
    int s = g_rowptr[w], e = g_rowptr[w + 1];
    int off = lane * 4;
    float4 a0 = make_float4(0.f, 0.f, 0.f, 0.f);
    float4 a1 = make_float4(0.f, 0.f, 0.f, 0.f);
    for (int j = s; j < e; ++j) {
        int c = g_cols[j];
        float v = g_vals[j];
        float4 x0 = *(const float4*)&src[(size_t)c * HID + off];
        float4 x1 = *(const float4*)&src[((size_t)NNODES + c) * HID + off];
        a0.x = fmaf(v, fmaxf(x0.x, 0.f), a0.x);
        a0.y = fmaf(v, fmaxf(x0.y, 0.f), a0.y);
        a0.z = fmaf(v, fmaxf(x0.z, 0.f), a0.z);
        a0.w = fmaf(v, fmaxf(x0.w, 0.f), a0.w);
        a1.x = fmaf(v, fmaxf(x1.x, 0.f), a1.x);
        a1.y = fmaf(v, fmaxf(x1.y, 0.f), a1.y);
        a1.z = fmaf(v, fmaxf(x1.z, 0.f), a1.z);
        a1.w = fmaf(v, fmaxf(x1.w, 0.f), a1.w);
    }
    *(float4*)&g_AGG[(size_t)w * HID + off] = a0;
    *(float4*)&g_AGG[((size_t)NNODES + w) * HID + off] = a1;
}

// ---------------- fused GEMM (f32x2): C = relu(A1)@Ws + AGG@Wf + bias (+res) ----------------
struct Frag { float4 va0, va1, vb0, vb1; };

__device__ __forceinline__ void fetch_tile(int t, const float* __restrict__ A1,
                                           const float* __restrict__ Ws,
                                           const float* __restrict__ Wf,
                                           int m0, int am, int ak4, int bk, int bn4,
                                           Frag& f) {
    int kg = t * 16;
    int ka = kg + ak4;
    if (ka < HID) {
        f.va0 = *(const float4*)&A1[(size_t)(m0 + am) * HID + ka];
        f.va1 = *(const float4*)&A1[(size_t)(m0 + am + 64) * HID + ka];
        f.va0.x = fmaxf(f.va0.x, 0.f); f.va0.y = fmaxf(f.va0.y, 0.f);
        f.va0.z = fmaxf(f.va0.z, 0.f); f.va0.w = fmaxf(f.va0.w, 0.f);
        f.va1.x = fmaxf(f.va1.x, 0.f); f.va1.y = fmaxf(f.va1.y, 0.f);
        f.va1.z = fmaxf(f.va1.z, 0.f); f.va1.w = fmaxf(f.va1.w, 0.f);
    } else {
        f.va0 = *(const float4*)&g_AGG[(size_t)(m0 + am) * HID + (ka - HID)];
        f.va1 = *(const float4*)&g_AGG[(size_t)(m0 + am + 64) * HID + (ka - HID)];
    }
    const float* W = (kg < HID) ? Ws : Wf;
    int kb = kg & (HID - 1);
    f.vb0 = *(const float4*)&W[(size_t)(kb + bk) * 128 + bn4];
    f.vb1 = *(const float4*)&W[(size_t)(kb + bk + 8) * 128 + bn4];
}

__global__ void __launch_bounds__(256) k_gemm(int mode,
        const float* __restrict__ Ws, const float* __restrict__ Wf,
        const float* __restrict__ bs, const float* __restrict__ bf) {
    const float* __restrict__ A1 = mode ? g_NET : g_X;
    float* __restrict__ C = mode ? g_X : g_NET;

    __shared__ float As[2][16][132];
    __shared__ float Bs[2][16][128];

    const int tid = threadIdx.x;
    const int m0 = blockIdx.x * 128;
    const int ak4 = (tid & 3) * 4;
    const int am  = tid >> 2;
    const int bn4 = (tid & 31) * 4;
    const int bk  = tid >> 5;
    const int tr  = (tid >> 4) * 4;
    const int tc  = (tid & 15) * 4;

    // acc[i][p]: row i (tr..tr+3, tr+64..tr+67), pair p: cols (tc,tc+1),(tc+2,tc+3),
    // (tc+64,tc+65),(tc+66,tc+67)
    long long acc[8][4];
    #pragma unroll
    for (int i = 0; i < 8; ++i)
        #pragma unroll
        for (int p = 0; p < 4; ++p) acc[i][p] = 0ll;

    Frag f;
    fetch_tile(0, A1, Ws, Wf, m0, am, ak4, bk, bn4, f);
    {
        As[0][ak4 + 0][am] = f.va0.x; As[0][ak4 + 1][am] = f.va0.y;
        As[0][ak4 + 2][am] = f.va0.z; As[0][ak4 + 3][am] = f.va0.w;
        As[0][ak4 + 0][am + 64] = f.va1.x; As[0][ak4 + 1][am + 64] = f.va1.y;
        As[0][ak4 + 2][am + 64] = f.va1.z; As[0][ak4 + 3][am + 64] = f.va1.w;
        *(float4*)&Bs[0][bk][bn4] = f.vb0;
        *(float4*)&Bs[0][bk + 8][bn4] = f.vb1;
    }
    __syncthreads();

    int buf = 0;
    #pragma unroll 1
    for (int t = 0; t < 16; ++t) {
        Frag nf;
        if (t < 15) fetch_tile(t + 1, A1, Ws, Wf, m0, am, ak4, bk, bn4, nf);
        #pragma unroll
        for (int k = 0; k < 16; ++k) {
            float a[8];
            *(float4*)&a[0] = *(const float4*)&As[buf][k][tr];
            *(float4*)&a[4] = *(const float4*)&As[buf][k][tr + 64];
            double2 t0 = *(const double2*)&Bs[buf][k][tc];
            double2 t1 = *(const double2*)&Bs[buf][k][tc + 64];
            long long b2[4];
            b2[0] = __double_as_longlong(t0.x);
            b2[1] = __double_as_longlong(t0.y);
            b2[2] = __double_as_longlong(t1.x);
            b2[3] = __double_as_longlong(t1.y);
            #pragma unroll
            for (int i = 0; i < 8; ++i) {
                long long a2;
                PACK2(a2, a[i]);
                FMA2(acc[i][0], a2, b2[0]);
                FMA2(acc[i][1], a2, b2[1]);
                FMA2(acc[i][2], a2, b2[2]);
                FMA2(acc[i][3], a2, b2[3]);
            }
        }
        if (t < 15) {
            int nb = buf ^ 1;
            As[nb][ak4 + 0][am] = nf.va0.x; As[nb][ak4 + 1][am] = nf.va0.y;
            As[nb][ak4 + 2][am] = nf.va0.z; As[nb][ak4 + 3][am] = nf.va0.w;
            As[nb][ak4 + 0][am + 64] = nf.va1.x; As[nb][ak4 + 1][am + 64] = nf.va1.y;
            As[nb][ak4 + 2][am + 64] = nf.va1.z; As[nb][ak4 + 3][am + 64] = nf.va1.w;
            *(float4*)&Bs[nb][bk][bn4] = nf.vb0;
            *(float4*)&Bs[nb][bk + 8][bn4] = nf.vb1;
        }
        __syncthreads();
        buf ^= 1;
    }

    float bias[8];
    #pragma unroll
    for (int j = 0; j < 4; ++j) {
        bias[j]     = bs[tc + j] + bf[tc + j];
        bias[4 + j] = bs[64 + tc + j] + bf[64 + tc + j];
    }
    #pragma unroll
    for (int ih = 0; ih < 2; ++ih)
        #pragma unroll
        for (int iv = 0; iv < 4; ++iv) {
            int m = m0 + ih * 64 + tr + iv;
            int ai = ih * 4 + iv;
            #pragma unroll
            for (int jh = 0; jh < 2; ++jh) {
                int n = jh * 64 + tc;
                float4 o;
                UNPACK2(o.x, o.y, acc[ai][jh * 2 + 0]);
                UNPACK2(o.z, o.w, acc[ai][jh * 2 + 1]);
                o.x += bias[jh * 4 + 0];
                o.y += bias[jh * 4 + 1];
                o.z += bias[jh * 4 + 2];
                o.w += bias[jh * 4 + 3];
                if (mode) {
                    float4 r = *(const float4*)&C[(size_t)m * HID + n];
                    o.x += r.x; o.y += r.y; o.z += r.z; o.w += r.w;
                }
                *(float4*)&C[(size_t)m * HID + n] = o;
            }
        }
}

// ---------------- final layer: Ys/Yf = relu(x) @ [Ws_out|Wf_out] ----------------
// out = Ys + biases (written here); Yf -> g_AGG[0 .. MROWS*3)
__global__ void k_fin_gemm(const float* __restrict__ Wso, const float* __restrict__ bso,
                           const float* __restrict__ Wfo, const float* __restrict__ bfo,
                           float* __restrict__ out) {
    int w = (blockIdx.x * blockDim.x + threadIdx.x) >> 5;
    int lane = threadIdx.x & 31;
    if (w >= MROWS) return;
    int k0 = lane * 4;
    float4 x = *(const float4*)&g_X[(size_t)w * HID + k0];
    float xv[4] = { fmaxf(x.x, 0.f), fmaxf(x.y, 0.f), fmaxf(x.z, 0.f), fmaxf(x.w, 0.f) };
    float s[6] = {0.f, 0.f, 0.f, 0.f, 0.f, 0.f};
    #pragma unroll
    for (int i = 0; i < 4; ++i) {
        int k = k0 + i;
        s[0] = fmaf(xv[i], Wso[k * 3 + 0], s[0]);
        s[1] = fmaf(xv[i], Wso[k * 3 + 1], s[1]);
        s[2] = fmaf(xv[i], Wso[k * 3 + 2], s[2]);
        s[3] = fmaf(xv[i], Wfo[k * 3 + 0], s[3]);
        s[4] = fmaf(xv[i], Wfo[k * 3 + 1], s[4]);
        s[5] = fmaf(xv[i], Wfo[k * 3 + 2], s[5]);
    }
    #pragma unroll
    for (int o = 16; o; o >>= 1) {
        #pragma unroll
        for (int c = 0; c < 6; ++c)
            s[c] += __shfl_down_sync(0xffffffffu, s[c], o);
    }
    if (lane == 0) {
        out[(size_t)w * 3 + 0] = s[0] + bso[0] + bfo[0];
        out[(size_t)w * 3 + 1] = s[1] + bso[1] + bfo[1];
        out[(size_t)w * 3 + 2] = s[2] + bso[2] + bfo[2];
        g_AGG[(size_t)w * 3 + 0] = s[3];
        g_AGG[(size_t)w * 3 + 1] = s[4];
        g_AGG[(size_t)w * 3 + 2] = s[5];
    }
}

// ---------------- final spmm on 3-wide: out += A * Yf (both batches) ----------------
__global__ void k_fin_spmm(float* __restrict__ out) {
    int n = blockIdx.x * blockDim.x + threadIdx.x;
    if (n >= NNODES) return;
    int s = g_rowptr[n], e = g_rowptr[n + 1];
    float a[6] = {0.f, 0.f, 0.f, 0.f, 0.f, 0.f};
    for (int j = s; j < e; ++j) {
        int c = g_cols[j];
        float v = g_vals[j];
        const float* y0 = &g_AGG[(size_t)c * 3];
        const float* y1 = &g_AGG[((size_t)NNODES + c) * 3];
        a[0] = fmaf(v, y0[0], a[0]);
        a[1] = fmaf(v, y0[1], a[1]);
        a[2] = fmaf(v, y0[2], a[2]);
        a[3] = fmaf(v, y1[0], a[3]);
        a[4] = fmaf(v, y1[1], a[4]);
        a[5] = fmaf(v, y1[2], a[5]);
    }
    float* o0 = &out[(size_t)n * 3];
    float* o1 = &out[((size_t)NNODES + n) * 3];
    o0[0] += a[0]; o0[1] += a[1]; o0[2] += a[2];
    o1[0] += a[3]; o1[1] += a[4]; o1[2] += a[5];
}

// ---------------- launch ----------------
extern "C" void kernel_launch(void* const* d_in, const int* in_sizes, int n_in,
                              void* d_out, int out_size) {
    const float* p        = (const float*)d_in[0];
    const float* adj_vals = (const float*)d_in[1];
    const int*   e_rows   = (const int*)d_in[2];
    const int*   e_cols   = (const int*)d_in[3];
    const float* W_init   = (const float*)d_in[4];
    const float* b_init   = (const float*)d_in[5];
    const float* Wf_b     = (const float*)d_in[6];
    const float* bf_b     = (const float*)d_in[7];
    const float* Ws_b     = (const float*)d_in[8];
    const float* bs_b     = (const float*)d_in[9];
    const float* Wf_out   = (const float*)d_in[10];
    const float* bf_out   = (const float*)d_in[11];
    const float* Ws_out   = (const float*)d_in[12];
    const float* bs_out   = (const float*)d_in[13];
    float* out = (float*)d_out;

    // CSR build (every call: no caching allowed)
    k_zero_cursor<<<(NNODES + 255) / 256, 256>>>();
    k_hist<<<(NEDGES + 255) / 256, 256>>>(e_rows);
    k_scan<<<1, 1024>>>();
    k_scatter<<<(NEDGES + 255) / 256, 256>>>(e_rows, e_cols, adj_vals);

    // x = p @ W_init + b_init
    k_init<<<(MROWS * 32 + 255) / 256, 256>>>(p, W_init, b_init);

    // 4 graph-conv layers (two residual blocks)
    for (int L = 0; L < 4; ++L) {
        int mode = L & 1;   // 0: X->NET, 1: NET->X (+residual)
        k_spmm<<<NNODES / 8, 256>>>(mode);
        k_gemm<<<MROWS / 128, 256>>>(mode,
                                     Ws_b + (size_t)L * HID * HID,
                                     Wf_b + (size_t)L * HID * HID,
                                     bs_b + (size_t)L * HID,
                                     bf_b + (size_t)L * HID);
    }

    // final 128 -> 3: GEMM first, then 3-wide spmm (linearity: spmm(X)@W == spmm(X@W))
    k_fin_gemm<<<(MROWS * 32 + 255) / 256, 256>>>(Ws_out, bs_out, Wf_out, bf_out, out);
    k_fin_spmm<<<(NNODES + 255) / 256, 256>>>(out);
}

// round 4
// speedup vs baseline: 1.5480x; 1.4978x over previous
#include <cuda_runtime.h>
#include <cuda_bf16.h>
#include <cstdint>

#define NNODES 40000
#define NEDGES 640000
#define HID    128
#define MROWS  80000   // BATCH * NNODES
#define KPAD   40      // padded k-stride (bf16 elems) -> 80B rows, ldmatrix conflict-free

// ---------------- device scratch (no allocations allowed) ----------------
__device__ float g_X[(size_t)MROWS * HID];
__device__ float g_NET[(size_t)MROWS * HID];
__device__ float g_AGG[(size_t)MROWS * HID];
__device__ int   g_rowptr[NNODES + 1];
__device__ int   g_cursor[NNODES];
__device__ int   g_cols[NEDGES];
__device__ float g_vals[NEDGES];
// pre-split transposed weights: [4 layers][8 chunks][n=128][k=KPAD] bf16 hi/lo
__device__ unsigned short g_Bh16[4 * 8 * 128 * KPAD];
__device__ unsigned short g_Bl16[4 * 8 * 128 * KPAD];

// ---------------- helpers ----------------
__device__ __forceinline__ uint32_t smem_u32(const void* p) {
    uint32_t a;
    asm("{ .reg .u64 t; cvta.to.shared.u64 t, %1; cvt.u32.u64 %0, t; }" : "=r"(a) : "l"(p));
    return a;
}

__device__ __forceinline__ void split_bf16(float v, unsigned short& hi, unsigned short& lo) {
    __nv_bfloat16 h = __float2bfloat16(v);
    float r = v - __bfloat162float(h);
    __nv_bfloat16 l = __float2bfloat16(r);
    hi = __bfloat16_as_ushort(h);
    lo = __bfloat16_as_ushort(l);
}

#define LDSM4(r0, r1, r2, r3, addr) \
    asm volatile("ldmatrix.sync.aligned.m8n8.x4.shared.b16 {%0,%1,%2,%3}, [%4];" \
        : "=r"(r0), "=r"(r1), "=r"(r2), "=r"(r3) : "r"(addr))

#define MMA16816(d, a, b0, b1) \
    asm volatile("mma.sync.aligned.m16n8k16.row.col.f32.bf16.bf16.f32 " \
        "{%0,%1,%2,%3}, {%4,%5,%6,%7}, {%8,%9}, {%0,%1,%2,%3};" \
        : "+f"((d)[0]), "+f"((d)[1]), "+f"((d)[2]), "+f"((d)[3]) \
        : "r"((a)[0]), "r"((a)[1]), "r"((a)[2]), "r"((a)[3]), "r"(b0), "r"(b1))

// ---------------- CSR build ----------------
__global__ void k_zero_cursor() {
    int i = blockIdx.x * blockDim.x + threadIdx.x;
    if (i < NNODES) g_cursor[i] = 0;
}

__global__ void k_hist(const int* __restrict__ rows) {
    int i = blockIdx.x * blockDim.x + threadIdx.x;
    if (i < NEDGES) atomicAdd(&g_cursor[rows[i]], 1);
}

__global__ void k_scan() {
    __shared__ int wsum[32];
    __shared__ int s_carry;
    int tid = threadIdx.x;
    int lane = tid & 31, wid = tid >> 5;
    if (tid == 0) { s_carry = 0; g_rowptr[0] = 0; }
    __syncthreads();
    for (int start = 0; start < NNODES; start += 1024) {
        int i = start + tid;
        int c = (i < NNODES) ? g_cursor[i] : 0;
        int v = c;
        #pragma unroll
        for (int o = 1; o < 32; o <<= 1) {
            int t = __shfl_up_sync(0xffffffffu, v, o);
            if (lane >= o) v += t;
        }
        if (lane == 31) wsum[wid] = v;
        __syncthreads();
        if (wid == 0) {
            int w = wsum[lane];
            #pragma unroll
            for (int o = 1; o < 32; o <<= 1) {
                int t = __shfl_up_sync(0xffffffffu, w, o);
                if (lane >= o) w += t;
            }
            wsum[lane] = w;
        }
        __syncthreads();
        int incl = v + (wid > 0 ? wsum[wid - 1] : 0) + s_carry;
        if (i < NNODES) { g_rowptr[i + 1] = incl; g_cursor[i] = incl - c; }
        int chunk_total = wsum[31];
        __syncthreads();
        if (tid == 0) s_carry += chunk_total;
        __syncthreads();
    }
}

__global__ void k_scatter(const int* __restrict__ rows, const int* __restrict__ cols,
                          const float* __restrict__ vals) {
    int i = blockIdx.x * blockDim.x + threadIdx.x;
    if (i < NEDGES) {
        int r = rows[i];
        int pos = atomicAdd(&g_cursor[r], 1);
        g_cols[pos] = cols[i];
        g_vals[pos] = vals[i];
    }
}

// ---------------- weight prep: transpose + bf16 split into padded panels ----------------
// B[n][gk] = W[gk][n], gk = c*32 + k, W = Ws (gk<128) else Wf.
__global__ void k_prepw16(const float* __restrict__ Ws_b, const float* __restrict__ Wf_b) {
    int idx = blockIdx.x * blockDim.x + threadIdx.x;   // (L, c, n, kq)
    if (idx >= 4 * 8 * 128 * 8) return;
    int kq = idx & 7;
    int n = (idx >> 3) & 127;
    int c = (idx >> 10) & 7;
    int L = idx >> 13;
    const float* Ws = Ws_b + (size_t)L * HID * HID;
    const float* Wf = Wf_b + (size_t)L * HID * HID;
    size_t base = ((size_t)(L * 8 + c) * 128 + n) * KPAD;
    #pragma unroll
    for (int e = 0; e < 4; ++e) {
        int k = kq * 4 + e;
        int gk = c * 32 + k;
        float v = (gk < HID) ? Ws[(size_t)gk * HID + n] : Wf[(size_t)(gk - HID) * HID + n];
        unsigned short hi, lo;
        split_bf16(v, hi, lo);
        g_Bh16[base + k] = hi;
        g_Bl16[base + k] = lo;
    }
}

// ---------------- init linear 3 -> 128 ----------------
__global__ void k_init(const float* __restrict__ p, const float* __restrict__ Wi,
                       const float* __restrict__ bi) {
    int idx = blockIdx.x * blockDim.x + threadIdx.x;
    if (idx >= MROWS * 32) return;
    int m = idx >> 5;
    int h = (idx & 31) * 4;
    float p0 = p[m * 3 + 0], p1 = p[m * 3 + 1], p2 = p[m * 3 + 2];
    float4 w0 = *(const float4*)&Wi[0 * HID + h];
    float4 w1 = *(const float4*)&Wi[1 * HID + h];
    float4 w2 = *(const float4*)&Wi[2 * HID + h];
    float4 bb = *(const float4*)&bi[h];
    float4 o;
    o.x = fmaf(p0, w0.x, fmaf(p1, w1.x, fmaf(p2, w2.x, bb.x)));
    o.y = fmaf(p0, w0.y, fmaf(p1, w1.y, fmaf(p2, w2.y, bb.y)));
    o.z = fmaf(p0, w0.z, fmaf(p1, w1.z, fmaf(p2, w2.z, bb.z)));
    o.w = fmaf(p0, w0.w, fmaf(p1, w1.w, fmaf(p2, w2.w, bb.w)));
    *(float4*)&g_X[(size_t)m * HID + h] = o;
}

// ---------------- spmm: AGG = A * relu(src), both batches per warp ----------------
__global__ void k_spmm(int sel) {
    const float* __restrict__ src = sel ? g_NET : g_X;
    int w = (blockIdx.x * blockDim.x + threadIdx.x) >> 5;
    int lane = threadIdx.x & 31;
    if (w >= NNODES) return;
    int s = g_rowptr[w], e = g_rowptr[w + 1];
    int off = lane * 4;
    float4 a0 = make_float4(0.f, 0.f, 0.f, 0.f);
    float4 a1 = make_float4(0.f, 0.f, 0.f, 0.f);
    for (int j = s; j < e; ++j) {
        int c = g_cols[j];
        float v = g_vals[j];
        float4 x0 = *(const float4*)&src[(size_t)c * HID + off];
        float4 x1 = *(const float4*)&src[((size_t)NNODES + c) * HID + off];
        a0.x = fmaf(v, fmaxf(x0.x, 0.f), a0.x);
        a0.y = fmaf(v, fmaxf(x0.y, 0.f), a0.y);
        a0.z = fmaf(v, fmaxf(x0.z, 0.f), a0.z);
        a0.w = fmaf(v, fmaxf(x0.w, 0.f), a0.w);
        a1.x = fmaf(v, fmaxf(x1.x, 0.f), a1.x);
        a1.y = fmaf(v, fmaxf(x1.y, 0.f), a1.y);
        a1.z = fmaf(v, fmaxf(x1.z, 0.f), a1.z);
        a1.w = fmaf(v, fmaxf(x1.w, 0.f), a1.w);
    }
    *(float4*)&g_AGG[(size_t)w * HID + off] = a0;
    *(float4*)&g_AGG[((size_t)NNODES + w) * HID + off] = a1;
}

// ---------------- mma.sync bf16 3-split GEMM ----------------
// C = relu(A1)@Ws + AGG@Wf + bias (+ residual if mode==1); A = [relu(A1)|AGG] : [M,256]
__global__ void __launch_bounds__(256, 2) k_gemm_mma(int mode, int L,
        const float* __restrict__ bs, const float* __restrict__ bf) {
    const float* __restrict__ A1 = mode ? g_NET : g_X;
    float* __restrict__ C = mode ? g_X : g_NET;

    __shared__ __align__(16) unsigned short sAh[128 * KPAD];
    __shared__ __align__(16) unsigned short sAl[128 * KPAD];
    __shared__ __align__(16) unsigned short sBh[128 * KPAD];
    __shared__ __align__(16) unsigned short sBl[128 * KPAD];
    __shared__ float s_bias[128];

    const int tid = threadIdx.x;
    const int lane = tid & 31, w = tid >> 5;
    const int m0 = blockIdx.x * 128;
    const int mw = (w & 3) * 32;        // warp M offset
    const int nw = (w >> 2) * 64;       // warp N offset

    if (tid < 128) s_bias[tid] = bs[tid] + bf[tid];

    const uint32_t aAh = smem_u32(sAh);
    const uint32_t aAl = smem_u32(sAl);
    const uint32_t aBh = smem_u32(sBh);
    const uint32_t aBl = smem_u32(sBl);

    // ldmatrix per-lane offsets
    const int a_row = lane & 15;
    const int a_k   = (lane >> 4) * 8;
    const int b_row = ((lane >> 4) & 1) * 8 + (lane & 7);
    const int b_k   = ((lane >> 3) & 1) * 8;

    float acc[2][8][4];
    #pragma unroll
    for (int i = 0; i < 2; ++i)
        #pragma unroll
        for (int j = 0; j < 8; ++j)
            #pragma unroll
            for (int q = 0; q < 4; ++q) acc[i][j][q] = 0.f;

    const unsigned short* __restrict__ Bh = g_Bh16 + (size_t)L * 8 * 128 * KPAD;
    const unsigned short* __restrict__ Bl = g_Bl16 + (size_t)L * 8 * 128 * KPAD;

    #pragma unroll 1
    for (int c = 0; c < 8; ++c) {
        // ---- stage A chunk: load f32, relu (act part), split to bf16 hi/lo ----
        const float* __restrict__ asrc = (c < 4) ? A1 : (const float*)g_AGG;
        const int kbase = (c & 3) * 32;
        #pragma unroll
        for (int i = 0; i < 4; ++i) {
            int idx = tid + i * 256;           // 0..1023
            int row = idx >> 3;
            int q = (idx & 7) * 4;
            float4 v = *(const float4*)&asrc[(size_t)(m0 + row) * HID + kbase + q];
            if (c < 4) {
                v.x = fmaxf(v.x, 0.f); v.y = fmaxf(v.y, 0.f);
                v.z = fmaxf(v.z, 0.f); v.w = fmaxf(v.w, 0.f);
            }
            unsigned short h[4], l[4];
            split_bf16(v.x, h[0], l[0]); split_bf16(v.y, h[1], l[1]);
            split_bf16(v.z, h[2], l[2]); split_bf16(v.w, h[3], l[3]);
            int eo = row * KPAD + q;
            *(uint2*)&sAh[eo] = *(uint2*)h;
            *(uint2*)&sAl[eo] = *(uint2*)l;
        }
        // ---- stage B chunk: flat copy of pre-split panels ----
        {
            const uint4* bh4 = (const uint4*)(Bh + (size_t)c * 128 * KPAD);
            const uint4* bl4 = (const uint4*)(Bl + (size_t)c * 128 * KPAD);
            uint4* dh = (uint4*)sBh;
            uint4* dl = (uint4*)sBl;
            #pragma unroll
            for (int i = tid; i < 128 * KPAD / 8; i += 256) {
                dh[i] = bh4[i];
                dl[i] = bl4[i];
            }
        }
        __syncthreads();

        // ---- compute: 2 k16 steps, 3-term bf16 MMA ----
        #pragma unroll
        for (int ks = 0; ks < 32; ks += 16) {
            uint32_t ah[2][4], al[2][4];
            #pragma unroll
            for (int mt = 0; mt < 2; ++mt) {
                uint32_t addr = aAh + (uint32_t)(((mw + mt * 16 + a_row) * KPAD + ks + a_k) * 2);
                LDSM4(ah[mt][0], ah[mt][1], ah[mt][2], ah[mt][3], addr);
                addr = aAl + (uint32_t)(((mw + mt * 16 + a_row) * KPAD + ks + a_k) * 2);
                LDSM4(al[mt][0], al[mt][1], al[mt][2], al[mt][3], addr);
            }
            #pragma unroll
            for (int nt4 = 0; nt4 < 4; ++nt4) {
                uint32_t bh[4], bl[4];
                uint32_t addr = aBh + (uint32_t)(((nw + nt4 * 16 + b_row) * KPAD + ks + b_k) * 2);
                LDSM4(bh[0], bh[1], bh[2], bh[3], addr);
                addr = aBl + (uint32_t)(((nw + nt4 * 16 + b_row) * KPAD + ks + b_k) * 2);
                LDSM4(bl[0], bl[1], bl[2], bl[3], addr);
                #pragma unroll
                for (int mt = 0; mt < 2; ++mt) {
                    #pragma unroll
                    for (int s = 0; s < 2; ++s) {
                        float* d = acc[mt][nt4 * 2 + s];
                        MMA16816(d, ah[mt], bh[2 * s], bh[2 * s + 1]);
                        MMA16816(d, ah[mt], bl[2 * s], bl[2 * s + 1]);
                        MMA16816(d, al[mt], bh[2 * s], bh[2 * s + 1]);
                    }
                }
            }
        }
        __syncthreads();
    }

    // ---- epilogue: bias + optional residual, fp32 out ----
    const int gid = lane >> 2, tig = lane & 3;
    #pragma unroll
    for (int mt = 0; mt < 2; ++mt) {
        #pragma unroll
        for (int nt = 0; nt < 8; ++nt) {
            int m = m0 + mw + mt * 16 + gid;
            int n = nw + nt * 8 + tig * 2;
            float b0 = s_bias[n], b1 = s_bias[n + 1];
            float2 o0 = make_float2(acc[mt][nt][0] + b0, acc[mt][nt][1] + b1);
            float2 o1 = make_float2(acc[mt][nt][2] + b0, acc[mt][nt][3] + b1);
            if (mode) {
                float2 r0 = *(const float2*)&C[(size_t)m * HID + n];
                float2 r1 = *(const float2*)&C[(size_t)(m + 8) * HID + n];
                o0.x += r0.x; o0.y += r0.y;
                o1.x += r1.x; o1.y += r1.y;
            }
            *(float2*)&C[(size_t)m * HID + n] = o0;
            *(float2*)&C[(size_t)(m + 8) * HID + n] = o1;
        }
    }
}

// ---------------- final layer: Ys/Yf = relu(x) @ [Ws_out|Wf_out] ----------------
__global__ void k_fin_gemm(const float* __restrict__ Wso, const float* __restrict__ bso,
                           const float* __restrict__ Wfo, const float* __restrict__ bfo,
                           float* __restrict__ out) {
    int w = (blockIdx.x * blockDim.x + threadIdx.x) >> 5;
    int lane = threadIdx.x & 31;
    if (w >= MROWS) return;
    int k0 = lane * 4;
    float4 x = *(const float4*)&g_X[(size_t)w * HID + k0];
    float xv[4] = { fmaxf(x.x, 0.f), fmaxf(x.y, 0.f), fmaxf(x.z, 0.f), fmaxf(x.w, 0.f) };
    float s[6] = {0.f, 0.f, 0.f, 0.f, 0.f, 0.f};
    #pragma unroll
    for (int i = 0; i < 4; ++i) {
        int k = k0 + i;
        s[0] = fmaf(xv[i], Wso[k * 3 + 0], s[0]);
        s[1] = fmaf(xv[i], Wso[k * 3 + 1], s[1]);
        s[2] = fmaf(xv[i], Wso[k * 3 + 2], s[2]);
        s[3] = fmaf(xv[i], Wfo[k * 3 + 0], s[3]);
        s[4] = fmaf(xv[i], Wfo[k * 3 + 1], s[4]);
        s[5] = fmaf(xv[i], Wfo[k * 3 + 2], s[5]);
    }
    #pragma unroll
    for (int o = 16; o; o >>= 1) {
        #pragma unroll
        for (int c = 0; c < 6; ++c)
            s[c] += __shfl_down_sync(0xffffffffu, s[c], o);
    }
    if (lane == 0) {
        out[(size_t)w * 3 + 0] = s[0] + bso[0] + bfo[0];
        out[(size_t)w * 3 + 1] = s[1] + bso[1] + bfo[1];
        out[(size_t)w * 3 + 2] = s[2] + bso[2] + bfo[2];
        g_AGG[(size_t)w * 3 + 0] = s[3];
        g_AGG[(size_t)w * 3 + 1] = s[4];
        g_AGG[(size_t)w * 3 + 2] = s[5];
    }
}

__global__ void k_fin_spmm(float* __restrict__ out) {
    int n = blockIdx.x * blockDim.x + threadIdx.x;
    if (n >= NNODES) return;
    int s = g_rowptr[n], e = g_rowptr[n + 1];
    float a[6] = {0.f, 0.f, 0.f, 0.f, 0.f, 0.f};
    for (int j = s; j < e; ++j) {
        int c = g_cols[j];
        float v = g_vals[j];
        const float* y0 = &g_AGG[(size_t)c * 3];
        const float* y1 = &g_AGG[((size_t)NNODES + c) * 3];
        a[0] = fmaf(v, y0[0], a[0]);
        a[1] = fmaf(v, y0[1], a[1]);
        a[2] = fmaf(v, y0[2], a[2]);
        a[3] = fmaf(v, y1[0], a[3]);
        a[4] = fmaf(v, y1[1], a[4]);
        a[5] = fmaf(v, y1[2], a[5]);
    }
    float* o0 = &out[(size_t)n * 3];
    float* o1 = &out[((size_t)NNODES + n) * 3];
    o0[0] += a[0]; o0[1] += a[1]; o0[2] += a[2];
    o1[0] += a[3]; o1[1] += a[4]; o1[2] += a[5];
}

// ---------------- launch ----------------
extern "C" void kernel_launch(void* const* d_in, const int* in_sizes, int n_in,
                              void* d_out, int out_size) {
    const float* p        = (const float*)d_in[0];
    const float* adj_vals = (const float*)d_in[1];
    const int*   e_rows   = (const int*)d_in[2];
    const int*   e_cols   = (const int*)d_in[3];
    const float* W_init   = (const float*)d_in[4];
    const float* b_init   = (const float*)d_in[5];
    const float* Wf_b     = (const float*)d_in[6];
    const float* bf_b     = (const float*)d_in[7];
    const float* Ws_b     = (const float*)d_in[8];
    const float* bs_b     = (const float*)d_in[9];
    const float* Wf_out   = (const float*)d_in[10];
    const float* bf_out   = (const float*)d_in[11];
    const float* Ws_out   = (const float*)d_in[12];
    const float* bs_out   = (const float*)d_in[13];
    float* out = (float*)d_out;

    // CSR build (every call: no caching allowed)
    k_zero_cursor<<<(NNODES + 255) / 256, 256>>>();
    k_hist<<<(NEDGES + 255) / 256, 256>>>(e_rows);
    k_scan<<<1, 1024>>>();
    k_scatter<<<(NEDGES + 255) / 256, 256>>>(e_rows, e_cols, adj_vals);

    // weight prep: transpose + bf16 split (cheap, overlaps with CSR serialization)
    k_prepw16<<<(4 * 8 * 128 * 8 + 255) / 256, 256>>>(Ws_b, Wf_b);

    // x = p @ W_init + b_init
    k_init<<<(MROWS * 32 + 255) / 256, 256>>>(p, W_init, b_init);

    // 4 graph-conv layers (two residual blocks)
    for (int L = 0; L < 4; ++L) {
        int mode = L & 1;   // 0: X->NET, 1: NET->X (+residual)
        k_spmm<<<NNODES / 8, 256>>>(mode);
        k_gemm_mma<<<MROWS / 128, 256>>>(mode, L,
                                         bs_b + (size_t)L * HID,
                                         bf_b + (size_t)L * HID);
    }

    // final 128 -> 3: GEMM then 3-wide spmm (linearity: spmm(X)@W == spmm(X@W))
    k_fin_gemm<<<(MROWS * 32 + 255) / 256, 256>>>(Ws_out, bs_out, Wf_out, bf_out, out);
    k_fin_spmm<<<(NNODES + 255) / 256, 256>>>(out);
}

// round 6
// speedup vs baseline: 1.5482x; 1.0001x over previous
#include <cuda_runtime.h>
#include <cuda_bf16.h>
#include <cstdint>

#define NNODES 40000
#define NEDGES 640000
#define HID    128
#define MROWS  80000   // BATCH * NNODES
#define KPAD   40      // padded k-stride (bf16 elems) -> 80B rows, ldmatrix conflict-free

// ---------------- device scratch (no allocations allowed) ----------------
__device__ float g_X[(size_t)MROWS * HID];
__device__ float g_NET[(size_t)MROWS * HID];
__device__ float g_AGG[(size_t)MROWS * HID];
__device__ int   g_rowptr[NNODES + 1];
__device__ int   g_cursor[NNODES];
__device__ int   g_cols[NEDGES];
__device__ float g_vals[NEDGES];
// pre-split transposed weights: [4 layers][8 chunks][n=128][k=KPAD] bf16 hi/lo
__device__ unsigned short g_Bh16[4 * 8 * 128 * KPAD];
__device__ unsigned short g_Bl16[4 * 8 * 128 * KPAD];

// ---------------- helpers ----------------
__device__ __forceinline__ uint32_t smem_u32(const void* p) {
    uint32_t a;
    asm("{ .reg .u64 t; cvta.to.shared.u64 t, %1; cvt.u32.u64 %0, t; }" : "=r"(a) : "l"(p));
    return a;
}

__device__ __forceinline__ void split_bf16(float v, unsigned short& hi, unsigned short& lo) {
    __nv_bfloat16 h = __float2bfloat16(v);
    float r = v - __bfloat162float(h);
    __nv_bfloat16 l = __float2bfloat16(r);
    hi = __bfloat16_as_ushort(h);
    lo = __bfloat16_as_ushort(l);
}

#define LDSM4(r0, r1, r2, r3, addr) \
    asm volatile("ldmatrix.sync.aligned.m8n8.x4.shared.b16 {%0,%1,%2,%3}, [%4];" \
        : "=r"(r0), "=r"(r1), "=r"(r2), "=r"(r3) : "r"(addr))

#define MMA16816(d, a, b0, b1) \
    asm volatile("mma.sync.aligned.m16n8k16.row.col.f32.bf16.bf16.f32 " \
        "{%0,%1,%2,%3}, {%4,%5,%6,%7}, {%8,%9}, {%0,%1,%2,%3};" \
        : "+f"((d)[0]), "+f"((d)[1]), "+f"((d)[2]), "+f"((d)[3]) \
        : "r"((a)[0]), "r"((a)[1]), "r"((a)[2]), "r"((a)[3]), "r"(b0), "r"(b1))

#define CP16(dst, src) \
    asm volatile("cp.async.cg.shared.global [%0], [%1], 16;" :: "r"(dst), "l"(src))
#define CP_COMMIT() asm volatile("cp.async.commit_group;" ::: "memory")
#define CP_WAIT0()  asm volatile("cp.async.wait_group 0;" ::: "memory")

// ---------------- CSR build ----------------
__global__ void k_zero_cursor() {
    int i = blockIdx.x * blockDim.x + threadIdx.x;
    if (i < NNODES) g_cursor[i] = 0;
}

__global__ void k_hist(const int* __restrict__ rows) {
    int i = blockIdx.x * blockDim.x + threadIdx.x;
    if (i < NEDGES) atomicAdd(&g_cursor[rows[i]], 1);
}

__global__ void k_scan() {
    __shared__ int wsum[32];
    __shared__ int s_carry;
    int tid = threadIdx.x;
    int lane = tid & 31, wid = tid >> 5;
    if (tid == 0) { s_carry = 0; g_rowptr[0] = 0; }
    __syncthreads();
    for (int start = 0; start < NNODES; start += 1024) {
        int i = start + tid;
        int c = (i < NNODES) ? g_cursor[i] : 0;
        int v = c;
        #pragma unroll
        for (int o = 1; o < 32; o <<= 1) {
            int t = __shfl_up_sync(0xffffffffu, v, o);
            if (lane >= o) v += t;
        }
        if (lane == 31) wsum[wid] = v;
        __syncthreads();
        if (wid == 0) {
            int w = wsum[lane];
            #pragma unroll
            for (int o = 1; o < 32; o <<= 1) {
                int t = __shfl_up_sync(0xffffffffu, w, o);
                if (lane >= o) w += t;
            }
            wsum[lane] = w;
        }
        __syncthreads();
        int incl = v + (wid > 0 ? wsum[wid - 1] : 0) + s_carry;
        if (i < NNODES) { g_rowptr[i + 1] = incl; g_cursor[i] = incl - c; }
        int chunk_total = wsum[31];
        __syncthreads();
        if (tid == 0) s_carry += chunk_total;
        __syncthreads();
    }
}

__global__ void k_scatter(const int* __restrict__ rows, const int* __restrict__ cols,
                          const float* __restrict__ vals) {
    int i = blockIdx.x * blockDim.x + threadIdx.x;
    if (i < NEDGES) {
        int r = rows[i];
        int pos = atomicAdd(&g_cursor[r], 1);
        g_cols[pos] = cols[i];
        g_vals[pos] = vals[i];
    }
}

// ---------------- weight prep: transpose + bf16 split into padded panels ----------------
__global__ void k_prepw16(const float* __restrict__ Ws_b, const float* __restrict__ Wf_b) {
    int idx = blockIdx.x * blockDim.x + threadIdx.x;   // (L, c, n, kq)
    if (idx >= 4 * 8 * 128 * 8) return;
    int kq = idx & 7;
    int n = (idx >> 3) & 127;
    int c = (idx >> 10) & 7;
    int L = idx >> 13;
    const float* Ws = Ws_b + (size_t)L * HID * HID;
    const float* Wf = Wf_b + (size_t)L * HID * HID;
    size_t base = ((size_t)(L * 8 + c) * 128 + n) * KPAD;
    #pragma unroll
    for (int e = 0; e < 4; ++e) {
        int k = kq * 4 + e;
        int gk = c * 32 + k;
        float v = (gk < HID) ? Ws[(size_t)gk * HID + n] : Wf[(size_t)(gk - HID) * HID + n];
        unsigned short hi, lo;
        split_bf16(v, hi, lo);
        g_Bh16[base + k] = hi;
        g_Bl16[base + k] = lo;
    }
}

// ---------------- init linear 3 -> 128 ----------------
__global__ void k_init(const float* __restrict__ p, const float* __restrict__ Wi,
                       const float* __restrict__ bi) {
    int idx = blockIdx.x * blockDim.x + threadIdx.x;
    if (idx >= MROWS * 32) return;
    int m = idx >> 5;
    int h = (idx & 31) * 4;
    float p0 = p[m * 3 + 0], p1 = p[m * 3 + 1], p2 = p[m * 3 + 2];
    float4 w0 = *(const float4*)&Wi[0 * HID + h];
    float4 w1 = *(const float4*)&Wi[1 * HID + h];
    float4 w2 = *(const float4*)&Wi[2 * HID + h];
    float4 bb = *(const float4*)&bi[h];
    float4 o;
    o.x = fmaf(p0, w0.x, fmaf(p1, w1.x, fmaf(p2, w2.x, bb.x)));
    o.y = fmaf(p0, w0.y, fmaf(p1, w1.y, fmaf(p2, w2.y, bb.y)));
    o.z = fmaf(p0, w0.z, fmaf(p1, w1.z, fmaf(p2, w2.z, bb.z)));
    o.w = fmaf(p0, w0.w, fmaf(p1, w1.w, fmaf(p2, w2.w, bb.w)));
    *(float4*)&g_X[(size_t)m * HID + h] = o;
}

// ---------------- spmm: AGG = A * relu(src), unroll-4 for MLP ----------------
__global__ void k_spmm(int sel) {
    const float* __restrict__ src = sel ? g_NET : g_X;
    int w = (blockIdx.x * blockDim.x + threadIdx.x) >> 5;
    int lane = threadIdx.x & 31;
    if (w >= NNODES) return;
    int s = g_rowptr[w], e = g_rowptr[w + 1];
    int off = lane * 4;
    float4 a0 = make_float4(0.f, 0.f, 0.f, 0.f);
    float4 a1 = make_float4(0.f, 0.f, 0.f, 0.f);
    int j = s;
    for (; j + 4 <= e; j += 4) {
        int cc[4]; float vv[4];
        #pragma unroll
        for (int u = 0; u < 4; ++u) { cc[u] = g_cols[j + u]; vv[u] = g_vals[j + u]; }
        float4 x0[4], x1[4];
        #pragma unroll
        for (int u = 0; u < 4; ++u) {
            x0[u] = *(const float4*)&src[(size_t)cc[u] * HID + off];
            x1[u] = *(const float4*)&src[((size_t)NNODES + cc[u]) * HID + off];
        }
        #pragma unroll
        for (int u = 0; u < 4; ++u) {
            float v = vv[u];
            a0.x = fmaf(v, fmaxf(x0[u].x, 0.f), a0.x);
            a0.y = fmaf(v, fmaxf(x0[u].y, 0.f), a0.y);
            a0.z = fmaf(v, fmaxf(x0[u].z, 0.f), a0.z);
            a0.w = fmaf(v, fmaxf(x0[u].w, 0.f), a0.w);
            a1.x = fmaf(v, fmaxf(x1[u].x, 0.f), a1.x);
            a1.y = fmaf(v, fmaxf(x1[u].y, 0.f), a1.y);
            a1.z = fmaf(v, fmaxf(x1[u].z, 0.f), a1.z);
            a1.w = fmaf(v, fmaxf(x1[u].w, 0.f), a1.w);
        }
    }
    for (; j < e; ++j) {
        int c = g_cols[j];
        float v = g_vals[j];
        float4 x0 = *(const float4*)&src[(size_t)c * HID + off];
        float4 x1 = *(const float4*)&src[((size_t)NNODES + c) * HID + off];
        a0.x = fmaf(v, fmaxf(x0.x, 0.f), a0.x);
        a0.y = fmaf(v, fmaxf(x0.y, 0.f), a0.y);
        a0.z = fmaf(v, fmaxf(x0.z, 0.f), a0.z);
        a0.w = fmaf(v, fmaxf(x0.w, 0.f), a0.w);
        a1.x = fmaf(v, fmaxf(x1.x, 0.f), a1.x);
        a1.y = fmaf(v, fmaxf(x1.y, 0.f), a1.y);
        a1.z = fmaf(v, fmaxf(x1.z, 0.f), a1.z);
        a1.w = fmaf(v, fmaxf(x1.w, 0.f), a1.w);
    }
    *(float4*)&g_AGG[(size_t)w * HID + off] = a0;
    *(float4*)&g_AGG[((size_t)NNODES + w) * HID + off] = a1;
}

// ---------------- mma.sync bf16 3-split GEMM, double-buffered + cp.async ----------------
// C = relu(A1)@Ws + AGG@Wf + bias (+ residual if mode==1); A = [relu(A1)|AGG] : [M,256]
// 512 threads: 16 warps, warp tile 32(M) x 32(N).
#define CHUNK_BYTES (128 * KPAD * 2)            // 10240 per array
#define BUF_BYTES   (4 * CHUNK_BYTES)           // Ah, Al, Bh, Bl
#define SMEM_DYN_GEMM (2 * BUF_BYTES)           // 81920

__global__ void __launch_bounds__(512, 1) k_gemm_mma(int mode, int L,
        const float* __restrict__ bs, const float* __restrict__ bf) {
    const float* __restrict__ A1 = mode ? g_NET : g_X;
    float* __restrict__ C = mode ? g_X : g_NET;

    extern __shared__ __align__(16) char dyn_smem[];
    __shared__ float s_bias[128];

    const int tid = threadIdx.x;
    const int lane = tid & 31, w = tid >> 5;
    const int m0 = blockIdx.x * 128;
    const int mw = (w & 3) * 32;        // warp M offset
    const int nw = (w >> 2) * 32;       // warp N offset

    if (tid < 128) s_bias[tid] = bs[tid] + bf[tid];

    const uint32_t sb = smem_u32(dyn_smem);
    // buffer b: Ah = sb + b*BUF, Al = +CHUNK, Bh = +2*CHUNK, Bl = +3*CHUNK

    // ldmatrix per-lane offsets
    const int a_row = lane & 15;
    const int a_k   = (lane >> 4) * 8;
    const int b_row = ((lane >> 4) & 1) * 8 + (lane & 7);
    const int b_k   = ((lane >> 3) & 1) * 8;

    float acc[2][4][4];
    #pragma unroll
    for (int i = 0; i < 2; ++i)
        #pragma unroll
        for (int j = 0; j < 4; ++j)
            #pragma unroll
            for (int q = 0; q < 4; ++q) acc[i][j][q] = 0.f;

    const unsigned short* __restrict__ Bh = g_Bh16 + (size_t)L * 8 * 128 * KPAD;
    const unsigned short* __restrict__ Bl = g_Bl16 + (size_t)L * 8 * 128 * KPAD;

    // A staging geometry: 1024 float4 per chunk; thread handles idx = tid, tid+512
    const int row0 = tid >> 3, row1 = (tid + 512) >> 3;
    const int q0 = (tid & 7) * 4, q1 = ((tid + 512) & 7) * 4;

    // ---- prologue: stage chunk 0 into buffer 0 ----
    {
        const float* __restrict__ asrc = A1;
        #pragma unroll
        for (int h = 0; h < 2; ++h) {
            int row = h ? row1 : row0;
            int q = h ? q1 : q0;
            float4 v = *(const float4*)&asrc[(size_t)(m0 + row) * HID + q];
            v.x = fmaxf(v.x, 0.f); v.y = fmaxf(v.y, 0.f);
            v.z = fmaxf(v.z, 0.f); v.w = fmaxf(v.w, 0.f);
            unsigned short hh[4], ll[4];
            split_bf16(v.x, hh[0], ll[0]); split_bf16(v.y, hh[1], ll[1]);
            split_bf16(v.z, hh[2], ll[2]); split_bf16(v.w, hh[3], ll[3]);
            uint32_t eo = (uint32_t)(row * KPAD + q) * 2;
            *(uint2*)(dyn_smem + eo) = *(uint2*)hh;
            *(uint2*)(dyn_smem + CHUNK_BYTES + eo) = *(uint2*)ll;
        }
        const char* bh_src = (const char*)Bh;
        const char* bl_src = (const char*)Bl;
        for (int i = tid; i < 640; i += 512) {
            CP16(sb + 2 * CHUNK_BYTES + i * 16, bh_src + i * 16);
            CP16(sb + 3 * CHUNK_BYTES + i * 16, bl_src + i * 16);
        }
        CP_COMMIT();
        CP_WAIT0();
    }
    __syncthreads();

    int buf = 0;
    #pragma unroll 1
    for (int c = 0; c < 8; ++c) {
        // ---- prefetch chunk c+1: A into regs (LDG now), B via cp.async ----
        float4 vn0, vn1;
        if (c < 7) {
            const float* __restrict__ asrc = (c + 1 < 4) ? A1 : (const float*)g_AGG;
            const int kbase = ((c + 1) & 3) * 32;
            vn0 = *(const float4*)&asrc[(size_t)(m0 + row0) * HID + kbase + q0];
            vn1 = *(const float4*)&asrc[(size_t)(m0 + row1) * HID + kbase + q1];
            const uint32_t nb = sb + (buf ^ 1) * BUF_BYTES;
            const char* bh_src = (const char*)(Bh + (size_t)(c + 1) * 128 * KPAD);
            const char* bl_src = (const char*)(Bl + (size_t)(c + 1) * 128 * KPAD);
            for (int i = tid; i < 640; i += 512) {
                CP16(nb + 2 * CHUNK_BYTES + i * 16, bh_src + i * 16);
                CP16(nb + 3 * CHUNK_BYTES + i * 16, bl_src + i * 16);
            }
            CP_COMMIT();
        }

        // ---- compute chunk c from buf ----
        const uint32_t cb = sb + buf * BUF_BYTES;
        #pragma unroll
        for (int ks = 0; ks < 32; ks += 16) {
            uint32_t ah[2][4], al[2][4];
            #pragma unroll
            for (int mt = 0; mt < 2; ++mt) {
                uint32_t ao = (uint32_t)(((mw + mt * 16 + a_row) * KPAD + ks + a_k) * 2);
                LDSM4(ah[mt][0], ah[mt][1], ah[mt][2], ah[mt][3], cb + ao);
                LDSM4(al[mt][0], al[mt][1], al[mt][2], al[mt][3], cb + CHUNK_BYTES + ao);
            }
            #pragma unroll
            for (int nt = 0; nt < 2; ++nt) {
                uint32_t bo = (uint32_t)(((nw + nt * 16 + b_row) * KPAD + ks + b_k) * 2);
                uint32_t bh4[4], bl4[4];
                LDSM4(bh4[0], bh4[1], bh4[2], bh4[3], cb + 2 * CHUNK_BYTES + bo);
                LDSM4(bl4[0], bl4[1], bl4[2], bl4[3], cb + 3 * CHUNK_BYTES + bo);
                #pragma unroll
                for (int mt = 0; mt < 2; ++mt) {
                    #pragma unroll
                    for (int s = 0; s < 2; ++s) {
                        float* d = acc[mt][nt * 2 + s];
                        MMA16816(d, ah[mt], bh4[2 * s], bh4[2 * s + 1]);
                        MMA16816(d, ah[mt], bl4[2 * s], bl4[2 * s + 1]);
                        MMA16816(d, al[mt], bh4[2 * s], bh4[2 * s + 1]);
                    }
                }
            }
        }

        // ---- finish staging chunk c+1: split A, wait B ----
        if (c < 7) {
            char* nbp = dyn_smem + (buf ^ 1) * BUF_BYTES;
            if (c + 1 < 4) {
                vn0.x = fmaxf(vn0.x, 0.f); vn0.y = fmaxf(vn0.y, 0.f);
                vn0.z = fmaxf(vn0.z, 0.f); vn0.w = fmaxf(vn0.w, 0.f);
                vn1.x = fmaxf(vn1.x, 0.f); vn1.y = fmaxf(vn1.y, 0.f);
                vn1.z = fmaxf(vn1.z, 0.f); vn1.w = fmaxf(vn1.w, 0.f);
            }
            unsigned short h0[4], l0[4], h1[4], l1[4];
            split_bf16(vn0.x, h0[0], l0[0]); split_bf16(vn0.y, h0[1], l0[1]);
            split_bf16(vn0.z, h0[2], l0[2]); split_bf16(vn0.w, h0[3], l0[3]);
            split_bf16(vn1.x, h1[0], l1[0]); split_bf16(vn1.y, h1[1], l1[1]);
            split_bf16(vn1.z, h1[2], l1[2]); split_bf16(vn1.w, h1[3], l1[3]);
            uint32_t eo0 = (uint32_t)(row0 * KPAD + q0) * 2;
            uint32_t eo1 = (uint32_t)(row1 * KPAD + q1) * 2;
            *(uint2*)(nbp + eo0) = *(uint2*)h0;
            *(uint2*)(nbp + CHUNK_BYTES + eo0) = *(uint2*)l0;
            *(uint2*)(nbp + eo1) = *(uint2*)h1;
            *(uint2*)(nbp + CHUNK_BYTES + eo1) = *(uint2*)l1;
            CP_WAIT0();
            __syncthreads();
            buf ^= 1;
        }
    }

    // ---- epilogue: bias + optional residual ----
    const int gid = lane >> 2, tig = lane & 3;
    #pragma unroll
    for (int mt = 0; mt < 2; ++mt) {
        #pragma unroll
        for (int nt = 0; nt < 4; ++nt) {
            int m = m0 + mw + mt * 16 + gid;
            int n = nw + nt * 8 + tig * 2;
            float b0 = s_bias[n], b1 = s_bias[n + 1];
            float2 o0 = make_float2(acc[mt][nt][0] + b0, acc[mt][nt][1] + b1);
            float2 o1 = make_float2(acc[mt][nt][2] + b0, acc[mt][nt][3] + b1);
            if (mode) {
                float2 r0 = *(const float2*)&C[(size_t)m * HID + n];
                float2 r1 = *(const float2*)&C[(size_t)(m + 8) * HID + n];
                o0.x += r0.x; o0.y += r0.y;
                o1.x += r1.x; o1.y += r1.y;
            }
            *(float2*)&C[(size_t)m * HID + n] = o0;
            *(float2*)&C[(size_t)(m + 8) * HID + n] = o1;
        }
    }
}

// ---------------- final layer: Ys/Yf = relu(x) @ [Ws_out|Wf_out] ----------------
__global__ void k_fin_gemm(const float* __restrict__ Wso, const float* __restrict__ bso,
                           const float* __restrict__ Wfo, const float* __restrict__ bfo,
                           float* __restrict__ out) {
    int w = (blockIdx.x * blockDim.x + threadIdx.x) >> 5;
    int lane = threadIdx.x & 31;
    if (w >= MROWS) return;
    int k0 = lane * 4;
    float4 x = *(const float4*)&g_X[(size_t)w * HID + k0];
    float xv[4] = { fmaxf(x.x, 0.f), fmaxf(x.y, 0.f), fmaxf(x.z, 0.f), fmaxf(x.w, 0.f) };
    float s[6] = {0.f, 0.f, 0.f, 0.f, 0.f, 0.f};
    #pragma unroll
    for (int i = 0; i < 4; ++i) {
        int k = k0 + i;
        s[0] = fmaf(xv[i], Wso[k * 3 + 0], s[0]);
        s[1] = fmaf(xv[i], Wso[k * 3 + 1], s[1]);
        s[2] = fmaf(xv[i], Wso[k * 3 + 2], s[2]);
        s[3] = fmaf(xv[i], Wfo[k * 3 + 0], s[3]);
        s[4] = fmaf(xv[i], Wfo[k * 3 + 1], s[4]);
        s[5] = fmaf(xv[i], Wfo[k * 3 + 2], s[5]);
    }
    #pragma unroll
    for (int o = 16; o; o >>= 1) {
        #pragma unroll
        for (int c = 0; c < 6; ++c)
            s[c] += __shfl_down_sync(0xffffffffu, s[c], o);
    }
    if (lane == 0) {
        out[(size_t)w * 3 + 0] = s[0] + bso[0] + bfo[0];
        out[(size_t)w * 3 + 1] = s[1] + bso[1] + bfo[1];
        out[(size_t)w * 3 + 2] = s[2] + bso[2] + bfo[2];
        g_AGG[(size_t)w * 3 + 0] = s[3];
        g_AGG[(size_t)w * 3 + 1] = s[4];
        g_AGG[(size_t)w * 3 + 2] = s[5];
    }
}

__global__ void k_fin_spmm(float* __restrict__ out) {
    int n = blockIdx.x * blockDim.x + threadIdx.x;
    if (n >= NNODES) return;
    int s = g_rowptr[n], e = g_rowptr[n + 1];
    float a[6] = {0.f, 0.f, 0.f, 0.f, 0.f, 0.f};
    for (int j = s; j < e; ++j) {
        int c = g_cols[j];
        float v = g_vals[j];
        const float* y0 = &g_AGG[(size_t)c * 3];
        const float* y1 = &g_AGG[((size_t)NNODES + c) * 3];
        a[0] = fmaf(v, y0[0], a[0]);
        a[1] = fmaf(v, y0[1], a[1]);
        a[2] = fmaf(v, y0[2], a[2]);
        a[3] = fmaf(v, y1[0], a[3]);
        a[4] = fmaf(v, y1[1], a[4]);
        a[5] = fmaf(v, y1[2], a[5]);
    }
    float* o0 = &out[(size_t)n * 3];
    float* o1 = &out[((size_t)NNODES + n) * 3];
    o0[0] += a[0]; o0[1] += a[1]; o0[2] += a[2];
    o1[0] += a[3]; o1[1] += a[4]; o1[2] += a[5];
}

// ---------------- launch ----------------
extern "C" void kernel_launch(void* const* d_in, const int* in_sizes, int n_in,
                              void* d_out, int out_size) {
    const float* p        = (const float*)d_in[0];
    const float* adj_vals = (const float*)d_in[1];
    const int*   e_rows   = (const int*)d_in[2];
    const int*   e_cols   = (const int*)d_in[3];
    const float* W_init   = (const float*)d_in[4];
    const float* b_init   = (const float*)d_in[5];
    const float* Wf_b     = (const float*)d_in[6];
    const float* bf_b     = (const float*)d_in[7];
    const float* Ws_b     = (const float*)d_in[8];
    const float* bs_b     = (const float*)d_in[9];
    const float* Wf_out   = (const float*)d_in[10];
    const float* bf_out   = (const float*)d_in[11];
    const float* Ws_out   = (const float*)d_in[12];
    const float* bs_out   = (const float*)d_in[13];
    float* out = (float*)d_out;

    static int smem_set = 0;
    cudaFuncSetAttribute(k_gemm_mma, cudaFuncAttributeMaxDynamicSharedMemorySize,
                         SMEM_DYN_GEMM);
    (void)smem_set;

    // CSR build (every call: no caching allowed)
    k_zero_cursor<<<(NNODES + 255) / 256, 256>>>();
    k_hist<<<(NEDGES + 255) / 256, 256>>>(e_rows);
    k_scan<<<1, 1024>>>();
    k_scatter<<<(NEDGES + 255) / 256, 256>>>(e_rows, e_cols, adj_vals);

    // weight prep: transpose + bf16 split
    k_prepw16<<<(4 * 8 * 128 * 8 + 255) / 256, 256>>>(Ws_b, Wf_b);

    // x = p @ W_init + b_init
    k_init<<<(MROWS * 32 + 255) / 256, 256>>>(p, W_init, b_init);

    // 4 graph-conv layers (two residual blocks)
    for (int L = 0; L < 4; ++L) {
        int mode = L & 1;   // 0: X->NET, 1: NET->X (+residual)
        k_spmm<<<NNODES / 8, 256>>>(mode);
        k_gemm_mma<<<MROWS / 128, 512, SMEM_DYN_GEMM>>>(mode, L,
                                                        bs_b + (size_t)L * HID,
                                                        bf_b + (size_t)L * HID);
    }

    // final 128 -> 3: GEMM then 3-wide spmm (linearity: spmm(X)@W == spmm(X@W))
    k_fin_gemm<<<(MROWS * 32 + 255) / 256, 256>>>(Ws_out, bs_out, Wf_out, bf_out, out);
    k_fin_spmm<<<(NNODES + 255) / 256, 256>>>(out);
}